// round 14
// baseline (speedup 1.0000x reference)
#include <cuda_runtime.h>
#include <cstdint>

#define FULLM 0xFFFFFFFFu
#define BIGF  3.402823466e+38f

__device__ float g_feat[256*1024*16]; // stage-1 per-point features (B,N,16)
__device__ float g_fs[256*512*8];     // squeezed features on xyz1 (B,512,8)
__device__ float g_psum[256*16*128];  // per-chunk partial sums of f2 (B,16,128)

__device__ __forceinline__ float lrelu(float x){ return x > 0.f ? x : 0.2f*x; }

// ---- packed f32x2 helpers (Blackwell) -------------------------------------
__device__ __forceinline__ unsigned long long pk(float lo, float hi){
    unsigned long long r;
    asm("mov.b64 %0, {%1, %2};" : "=l"(r) : "f"(lo), "f"(hi));
    return r;
}
__device__ __forceinline__ float2 upk(unsigned long long v){
    float2 r;
    asm("mov.b64 {%0, %1}, %2;" : "=f"(r.x), "=f"(r.y) : "l"(v));
    return r;
}
__device__ __forceinline__ unsigned long long ffma2(
    unsigned long long a, unsigned long long b, unsigned long long c){
    unsigned long long d;
    asm("fma.rn.f32x2 %0, %1, %2, %3;" : "=l"(d) : "l"(a), "l"(b), "l"(c));
    return d;
}

__device__ __forceinline__ float qdist(const float4& v, float qx, float qy, float qz){
    // d' = |p|^2 - 2 q.p  (query-constant |q|^2 dropped: order-preserving)
    return fmaf(-2.f, fmaf(qx, v.x, fmaf(qy, v.y, qz*v.z)), v.w);
}

// Order-preserving 16-bit key of a float (monotone non-decreasing).
__device__ __forceinline__ unsigned f2o16(float f){
    unsigned b = __float_as_uint(f);
    b ^= (unsigned)(((int)b) >> 31) | 0x80000000u;
    return b >> 16;
}

// Value-only bitonic sort of 32 floats across a warp (ascending).
__device__ __forceinline__ float bsort32_val(float s, int lane){
    #pragma unroll
    for (int k = 2; k <= 32; k <<= 1){
        #pragma unroll
        for (int j = k >> 1; j > 0; j >>= 1){
            float o = __shfl_xor_sync(FULLM, s, j);
            bool keepmin = ((lane & j) == 0) == ((lane & k) == 0);
            float mn = fminf(s, o), mx = fmaxf(s, o);
            s = keepmin ? mn : mx;
        }
    }
    return s;
}

// Bitonic sort of 32 (d,i) pairs across a warp, ascending lex (d, then i).
__device__ __forceinline__ void bsort32_pair(float& d, int& i, int lane){
    #pragma unroll
    for (int k = 2; k <= 32; k <<= 1){
        #pragma unroll
        for (int j = k >> 1; j > 0; j >>= 1){
            float od = __shfl_xor_sync(FULLM, d, j);
            int   oi = __shfl_xor_sync(FULLM, i, j);
            bool lower = (lane & j) == 0;
            bool asc   = (lane & k) == 0;
            bool osm   = (od < d) || (od == d && oi < i);
            bool take  = (lower == asc) ? osm : !osm;
            if (take){ d = od; i = oi; }
        }
    }
}

// Exact top-16 of NT*32 candidates. sp holds (x,y,z,|p|^2) per point.
// dc16: per-warp NT*32 u16 distance-key cache (filled in phase 1; phase 3
// filters on 16-bit keys — a provable SUPERSET of d<=thr; exact fp32
// distances are recomputed only for qualifiers, so the selected set is
// identical to exact lax.top_k).
// Returns the set of 16 nearest indices distributed on lanes 0..15.
template<int NT>
__device__ __forceinline__ int knn16_select(
    const float4* __restrict__ sp, unsigned short* __restrict__ dc16,
    float qx, float qy, float qz, int lane,
    float* scand, int* sidxs)
{
    // --- phase 1: distances -> 16-bit key cache + per-lane min (4 chains) --
    float m0 = BIGF, m1 = BIGF, m2 = BIGF, m3 = BIGF;
    #pragma unroll
    for (int t = 0; t < NT; t += 4){
        float d0 = qdist(sp[lane + (t  )*32], qx, qy, qz);
        float d1 = qdist(sp[lane + (t+1)*32], qx, qy, qz);
        float d2 = qdist(sp[lane + (t+2)*32], qx, qy, qz);
        float d3 = qdist(sp[lane + (t+3)*32], qx, qy, qz);
        dc16[(t  )*32 + lane] = (unsigned short)f2o16(d0);
        dc16[(t+1)*32 + lane] = (unsigned short)f2o16(d1);
        dc16[(t+2)*32 + lane] = (unsigned short)f2o16(d2);
        dc16[(t+3)*32 + lane] = (unsigned short)f2o16(d3);
        m0 = fminf(m0, d0); m1 = fminf(m1, d1);
        m2 = fminf(m2, d2); m3 = fminf(m3, d3);
    }
    float bd = fminf(fminf(m0, m1), fminf(m2, m3));

    // --- phase 2: threshold = 16th-smallest lane minimum (valid bound) -----
    float thr = __shfl_sync(FULLM, bsort32_val(bd, lane), 15);
    unsigned thr16u = f2o16(thr);   // floor key: key(d)<=key(thr) superset of d<=thr

    // --- phase 3: bitmask filter on cached 16-bit keys ----------------------
    unsigned qmask = 0;
    #pragma unroll
    for (int t = 0; t < NT; t++){
        if ((unsigned)dc16[t*32 + lane] <= thr16u) qmask |= (1u << t);
    }
    int myc = __popc(qmask);
    // inclusive shfl scan -> exclusive offset + warp total
    int off = myc;
    #pragma unroll
    for (int s = 1; s < 32; s <<= 1){
        int o = __shfl_up_sync(FULLM, off, s);
        if (lane >= s) off += o;
    }
    int cnt = __shfl_sync(FULLM, off, 31);
    off -= myc;

    scand[lane] = BIGF; sidxs[lane] = 0x7FFFFFFF;
    __syncwarp();
    {
        unsigned mm = qmask;
        int pos = off;
        while (mm){
            int t = __ffs(mm) - 1;
            mm &= mm - 1;
            if (pos < 32){
                float d = qdist(sp[lane + t*32], qx, qy, qz);   // exact fp32
                scand[pos] = d; sidxs[pos] = lane + t*32;
            }
            pos++;
        }
    }
    __syncwarp();

    int kidx;
    if (cnt <= 32){
        float d2 = scand[lane]; int i2 = sidxs[lane];
        // value-only sort to find the 16th-smallest distance in the buffer
        float thr16 = __shfl_sync(FULLM, bsort32_val(d2, lane), 15);
        unsigned lt = (1u << lane) - 1u;
        unsigned sel = __ballot_sync(FULLM, d2 <= thr16);
        if (__popc(sel) == 16){
            // no boundary tie: selected lanes ARE the exact top-16 set
            __syncwarp();
            if (d2 <= thr16){
                int pos = __popc(sel & lt);
                sidxs[pos] = i2;
            }
            __syncwarp();
            kidx = sidxs[lane & 15];
        } else {
            // boundary tie on distance: exact lex (d, idx) sort
            bsort32_pair(d2, i2, lane);
            kidx = i2;
        }
    } else {
        // --- rare fallback: progressive argmin with lex exclusion ----------
        float lastD = -BIGF; int lastI = -1; kidx = 0x7FFFFFFF;
        for (int r = 0; r < 16; r++){
            float cbd = BIGF; int cbi = 0x7FFFFFFF;
            #pragma unroll
            for (int t = 0; t < NT; t++){
                int j = lane + t*32;
                float d = qdist(sp[j], qx, qy, qz);
                bool gt = (d > lastD) || (d == lastD && j > lastI);
                if (gt && ((d < cbd) || (d == cbd && j < cbi))){ cbd = d; cbi = j; }
            }
            #pragma unroll
            for (int off2 = 16; off2 > 0; off2 >>= 1){
                float od = __shfl_down_sync(FULLM, cbd, off2);
                int   oi = __shfl_down_sync(FULLM, cbi, off2);
                if (od < cbd || (od == cbd && oi < cbi)){ cbd = od; cbi = oi; }
            }
            lastD = __shfl_sync(FULLM, cbd, 0);
            lastI = __shfl_sync(FULLM, cbi, 0);
            if (lane == r) kidx = lastI;
        }
    }
    return kidx;
}

// ---------------------------------------------------------------------------
// Kernel A: f = lrelu(LN(lrelu(LN(xyz@W0+b0))@W1+b1))  per point.
// Weight loads vectorized to float4 (arithmetic order unchanged).
// ---------------------------------------------------------------------------
__global__ void __launch_bounds__(256) kA(
    const float* __restrict__ pc,
    const float* __restrict__ W0, const float* __restrict__ b0,
    const float* __restrict__ g0, const float* __restrict__ be0,
    const float* __restrict__ W1, const float* __restrict__ b1,
    const float* __restrict__ g1, const float* __restrict__ be1)
{
    int i = blockIdx.x*256 + threadIdx.x;
    int b = i >> 10, n = i & 1023;
    const float* p = pc + (size_t)b*3072;
    float x = p[n], y = p[1024+n], z = p[2048+n];

    const float4* W0_4  = reinterpret_cast<const float4*>(W0);
    const float4* b0_4  = reinterpret_cast<const float4*>(b0);
    const float4* g0_4  = reinterpret_cast<const float4*>(g0);
    const float4* be0_4 = reinterpret_cast<const float4*>(be0);
    const float4* b1_4  = reinterpret_cast<const float4*>(b1);
    const float4* g1_4  = reinterpret_cast<const float4*>(g1);
    const float4* be1_4 = reinterpret_cast<const float4*>(be1);

    float t[16];
    #pragma unroll
    for (int g=0; g<4; g++){
        float4 w0r = __ldg(&W0_4[g]);
        float4 w1r = __ldg(&W0_4[4+g]);
        float4 w2r = __ldg(&W0_4[8+g]);
        float4 bb  = __ldg(&b0_4[g]);
        t[4*g+0] = fmaf(x, w0r.x, fmaf(y, w1r.x, fmaf(z, w2r.x, bb.x)));
        t[4*g+1] = fmaf(x, w0r.y, fmaf(y, w1r.y, fmaf(z, w2r.y, bb.y)));
        t[4*g+2] = fmaf(x, w0r.z, fmaf(y, w1r.z, fmaf(z, w2r.z, bb.z)));
        t[4*g+3] = fmaf(x, w0r.w, fmaf(y, w1r.w, fmaf(z, w2r.w, bb.w)));
    }
    {
        float m=0.f;
        #pragma unroll
        for (int c=0;c<16;c++) m += t[c];
        m *= (1.f/16.f);
        float v=0.f;
        #pragma unroll
        for (int c=0;c<16;c++){ float dd=t[c]-m; v = fmaf(dd,dd,v); }
        v *= (1.f/16.f);
        float inv = rsqrtf(v + 1e-5f);
        #pragma unroll
        for (int g=0; g<4; g++){
            float4 gg = __ldg(&g0_4[g]);
            float4 bb = __ldg(&be0_4[g]);
            t[4*g+0] = lrelu(fmaf((t[4*g+0]-m)*inv, gg.x, bb.x));
            t[4*g+1] = lrelu(fmaf((t[4*g+1]-m)*inv, gg.y, bb.y));
            t[4*g+2] = lrelu(fmaf((t[4*g+2]-m)*inv, gg.z, bb.z));
            t[4*g+3] = lrelu(fmaf((t[4*g+3]-m)*inv, gg.w, bb.w));
        }
    }
    float4 acc0 = __ldg(&b1_4[0]);
    float4 acc1 = __ldg(&b1_4[1]);
    float4 acc2 = __ldg(&b1_4[2]);
    float4 acc3 = __ldg(&b1_4[3]);
    #pragma unroll
    for (int c=0;c<16;c++){
        float tc = t[c];
        const float4* wr = reinterpret_cast<const float4*>(W1 + c*16);
        float4 w0v = __ldg(&wr[0]);
        float4 w1v = __ldg(&wr[1]);
        float4 w2v = __ldg(&wr[2]);
        float4 w3v = __ldg(&wr[3]);
        acc0.x = fmaf(tc, w0v.x, acc0.x); acc0.y = fmaf(tc, w0v.y, acc0.y);
        acc0.z = fmaf(tc, w0v.z, acc0.z); acc0.w = fmaf(tc, w0v.w, acc0.w);
        acc1.x = fmaf(tc, w1v.x, acc1.x); acc1.y = fmaf(tc, w1v.y, acc1.y);
        acc1.z = fmaf(tc, w1v.z, acc1.z); acc1.w = fmaf(tc, w1v.w, acc1.w);
        acc2.x = fmaf(tc, w2v.x, acc2.x); acc2.y = fmaf(tc, w2v.y, acc2.y);
        acc2.z = fmaf(tc, w2v.z, acc2.z); acc2.w = fmaf(tc, w2v.w, acc2.w);
        acc3.x = fmaf(tc, w3v.x, acc3.x); acc3.y = fmaf(tc, w3v.y, acc3.y);
        acc3.z = fmaf(tc, w3v.z, acc3.z); acc3.w = fmaf(tc, w3v.w, acc3.w);
    }
    float u[16] = {acc0.x,acc0.y,acc0.z,acc0.w, acc1.x,acc1.y,acc1.z,acc1.w,
                   acc2.x,acc2.y,acc2.z,acc2.w, acc3.x,acc3.y,acc3.z,acc3.w};
    {
        float m=0.f;
        #pragma unroll
        for (int c=0;c<16;c++) m += u[c];
        m *= (1.f/16.f);
        float v=0.f;
        #pragma unroll
        for (int c=0;c<16;c++){ float dd=u[c]-m; v = fmaf(dd,dd,v); }
        v *= (1.f/16.f);
        float inv = rsqrtf(v + 1e-5f);
        #pragma unroll
        for (int g=0; g<4; g++){
            float4 gg = __ldg(&g1_4[g]);
            float4 bb = __ldg(&be1_4[g]);
            u[4*g+0] = lrelu(fmaf((u[4*g+0]-m)*inv, gg.x, bb.x));
            u[4*g+1] = lrelu(fmaf((u[4*g+1]-m)*inv, gg.y, bb.y));
            u[4*g+2] = lrelu(fmaf((u[4*g+2]-m)*inv, gg.z, bb.z));
            u[4*g+3] = lrelu(fmaf((u[4*g+3]-m)*inv, gg.w, bb.w));
        }
    }
    float4* o4 = reinterpret_cast<float4*>(g_feat + (size_t)i*16);
    o4[0] = make_float4(u[0],u[1],u[2],u[3]);
    o4[1] = make_float4(u[4],u[5],u[6],u[7]);
    o4[2] = make_float4(u[8],u[9],u[10],u[11]);
    o4[3] = make_float4(u[12],u[13],u[14],u[15]);
}

// ---------------------------------------------------------------------------
// Kernel B: pointconv1 (K=16 NN of 512 queries over 1024 pts) + fused squeeze
// Persistent grid of 444 blocks (148 SMs x occ 3). 16384 chunks of 8 queries;
// contiguous runs of 36/37 chunks per block. 16-bit distance-key cache.
// ---------------------------------------------------------------------------
#define KB_BLOCKS 444

__global__ void __launch_bounds__(256, 3) kB(
    const float* __restrict__ pc,
    const float* __restrict__ Wp, const float* __restrict__ bp,
    const float* __restrict__ Ws, const float* __restrict__ bsv)
{
    __shared__ __align__(16) float4 sp4[1024];
    __shared__ __align__(16) float  sg[8][16][20];
    __shared__ __align__(16) float  scand[8][32];
    __shared__ __align__(16) int    sidxs[8][32];
    __shared__ __align__(16) float  smx[8][32];
    __shared__ __align__(16) unsigned short dc16[8][1024];

    int tid  = threadIdx.x;
    int lane = tid & 31;
    int w    = tid >> 5;
    int bid  = blockIdx.x;

    // contiguous chunk partition: 16384 = 400*37 + 44*36
    int start, cnt;
    if (bid < 400){ start = bid*37;               cnt = 37; }
    else          { start = 14800 + (bid-400)*36; cnt = 36; }

    // packed per-lane GEMM weights: lane = output channel
    unsigned long long wp[9];
    #pragma unroll
    for (int c=0;c<9;c++)
        wp[c] = pk(__ldg(&Wp[(2*c)*32 + lane]), __ldg(&Wp[(2*c+1)*32 + lane]));
    float wr18 = __ldg(&Wp[18*32 + lane]);
    unsigned long long accp = pk(__ldg(&bp[lane]), 0.f);

    // squeeze weights: lane handles output j = lane&7 over c in [cb, cb+8)
    int jq = lane & 7, cb = (lane >> 3) * 8;
    unsigned long long wsp[4];
    #pragma unroll
    for (int i=0;i<4;i++)
        wsp[i] = pk(__ldg(&Ws[(cb+2*i)*8 + jq]), __ldg(&Ws[(cb+2*i+1)*8 + jq]));
    float bsq = __ldg(&bsv[jq]);

    int curB = -1;
    for (int ci = start; ci < start + cnt; ci++){
        int b    = ci >> 6;
        int m    = ((ci & 63) << 3) + w;              // this warp's query
        if (b != curB){
            __syncthreads();                           // old sp4 fully consumed
            const float* p = pc + (size_t)b*3072;
            for (int n = tid; n < 1024; n += 256){
                float X = p[n], Y = p[1024+n], Z = p[2048+n];
                sp4[n] = make_float4(X, Y, Z, fmaf(X,X, fmaf(Y,Y, Z*Z)));
            }
            __syncthreads();
            curB = b;
        }

        int qi = 2*m;                                  // xyz1[m] == xyz0[2m]
        float4 q = sp4[qi];

        int kidx = knn16_select<32>(sp4, &dc16[w][0], q.x, q.y, q.z, lane,
                                    &scand[w][0], &sidxs[w][0]);

        // --- full-warp gather into per-warp smem g[16][20] ------------------
        __syncwarp();
        {
            int j = __shfl_sync(FULLM, kidx, lane & 15);
            float* gr = &sg[w][lane & 15][0];
            const float4* fr = reinterpret_cast<const float4*>(
                g_feat + ((size_t)b*1024 + j)*16);
            if (lane < 16){
                float4 xj = sp4[j];
                float4 f0 = fr[0], f1 = fr[1];
                gr[0]=xj.x-q.x; gr[1]=xj.y-q.y; gr[2]=xj.z-q.z;
                gr[3]=f0.x;  gr[4]=f0.y;  gr[5]=f0.z;  gr[6]=f0.w;
                gr[7]=f1.x;  gr[8]=f1.y;  gr[9]=f1.z;  gr[10]=f1.w;
            } else {
                float4 f2v = fr[2], f3 = fr[3];
                gr[11]=f2v.x; gr[12]=f2v.y; gr[13]=f2v.z; gr[14]=f2v.w;
                gr[15]=f3.x;  gr[16]=f3.y;  gr[17]=f3.z;  gr[18]=f3.w;
            }
        }
        __syncwarp();

        // --- GEMM (lane = output channel) via packed FFMA2 + maxpool -------
        float mx = -BIGF;
        #pragma unroll 4
        for (int k=0;k<16;k++){
            const float* gr = &sg[w][k][0];
            ulonglong2 pA = *reinterpret_cast<const ulonglong2*>(gr);
            ulonglong2 pB = *reinterpret_cast<const ulonglong2*>(gr+4);
            ulonglong2 pC = *reinterpret_cast<const ulonglong2*>(gr+8);
            ulonglong2 pD = *reinterpret_cast<const ulonglong2*>(gr+12);
            unsigned long long pE = *reinterpret_cast<const unsigned long long*>(gr+16);
            float  g18 = gr[18];
            unsigned long long acc = accp;
            acc = ffma2(pA.x, wp[0], acc);
            acc = ffma2(pA.y, wp[1], acc);
            acc = ffma2(pB.x, wp[2], acc);
            acc = ffma2(pB.y, wp[3], acc);
            acc = ffma2(pC.x, wp[4], acc);
            acc = ffma2(pC.y, wp[5], acc);
            acc = ffma2(pD.x, wp[6], acc);
            acc = ffma2(pD.y, wp[7], acc);
            acc = ffma2(pE,   wp[8], acc);
            float2 s = upk(acc);
            float a = fmaf(g18, wr18, s.x + s.y);
            mx = fmaxf(mx, lrelu(a));
        }

        // --- fused squeeze via smem transpose: fs = lrelu(mx @ Ws + bs) -----
        smx[w][lane] = mx;
        __syncwarp();
        const unsigned long long* mp =
            reinterpret_cast<const unsigned long long*>(&smx[w][cb]);
        unsigned long long s2 = pk(0.f, 0.f);
        s2 = ffma2(mp[0], wsp[0], s2);
        s2 = ffma2(mp[1], wsp[1], s2);
        s2 = ffma2(mp[2], wsp[2], s2);
        s2 = ffma2(mp[3], wsp[3], s2);
        float2 sv = upk(s2);
        float s = sv.x + sv.y;
        s += __shfl_down_sync(FULLM, s, 16);
        s += __shfl_down_sync(FULLM, s, 8);
        if (lane < 8)
            g_fs[((size_t)b*512 + m)*8 + jq] = lrelu(s + bsq);
    }
}

// ---------------------------------------------------------------------------
// Kernel C: pointconv2 (128 queries, 512 candidates, 11ch -> 128ch) with
// fused per-chunk column-sum. Persistent grid of 444 blocks; 4096 chunks of
// 8 queries (16 chunks/batch), contiguous runs of 9/10 chunks per block.
// ---------------------------------------------------------------------------
#define KC_BLOCKS 444

__global__ void __launch_bounds__(256, 3) kC(
    const float* __restrict__ pc,
    const float* __restrict__ Wc, const float* __restrict__ bc)
{
    __shared__ __align__(16) float4 sp4[512];
    __shared__ __align__(16) float  sf[512*8];
    __shared__ __align__(16) float  sg[8][16][12];
    __shared__ __align__(16) float  scand[8][32];
    __shared__ __align__(16) int    sidxs[8][32];
    __shared__ float  sacc[8][128];
    __shared__ __align__(16) unsigned short dc16[8][512];

    int tid  = threadIdx.x;
    int lane = tid & 31;
    int w    = tid >> 5;
    int bid  = blockIdx.x;

    // contiguous chunk partition: 4096 = 100*10 + 344*9
    int start, cnt;
    if (bid < 100){ start = bid*10;              cnt = 10; }
    else          { start = 1000 + (bid-100)*9;  cnt = 9;  }

    // packed weights for 4 output channels per lane (lane, lane+32, +64, +96)
    unsigned long long wq0[5], wq1[5], wq2[5], wq3[5];
    #pragma unroll
    for (int c=0;c<5;c++){
        wq0[c] = pk(__ldg(&Wc[(2*c)*128 + lane]),      __ldg(&Wc[(2*c+1)*128 + lane]));
        wq1[c] = pk(__ldg(&Wc[(2*c)*128 + lane + 32]), __ldg(&Wc[(2*c+1)*128 + lane + 32]));
        wq2[c] = pk(__ldg(&Wc[(2*c)*128 + lane + 64]), __ldg(&Wc[(2*c+1)*128 + lane + 64]));
        wq3[c] = pk(__ldg(&Wc[(2*c)*128 + lane + 96]), __ldg(&Wc[(2*c+1)*128 + lane + 96]));
    }
    float w10_0 = __ldg(&Wc[10*128 + lane]),      w10_1 = __ldg(&Wc[10*128 + lane + 32]);
    float w10_2 = __ldg(&Wc[10*128 + lane + 64]), w10_3 = __ldg(&Wc[10*128 + lane + 96]);
    unsigned long long bp0 = pk(__ldg(&bc[lane]),     0.f);
    unsigned long long bp1 = pk(__ldg(&bc[lane+32]),  0.f);
    unsigned long long bp2 = pk(__ldg(&bc[lane+64]),  0.f);
    unsigned long long bp3 = pk(__ldg(&bc[lane+96]),  0.f);

    int curB = -1;
    for (int ci = start; ci < start + cnt; ci++){
        int b     = ci >> 4;
        int chunk = ci & 15;
        int m2    = (chunk << 3) + w;                 // this warp's query
        if (b != curB){
            __syncthreads();                           // old sp4/sf consumed
            const float* p = pc + (size_t)b*3072;
            for (int m = tid; m < 512; m += 256){
                float X = p[2*m], Y = p[1024+2*m], Z = p[2048+2*m];
                sp4[m] = make_float4(X, Y, Z, fmaf(X,X, fmaf(Y,Y, Z*Z)));
            }
            const float4* src = reinterpret_cast<const float4*>(g_fs + (size_t)b*4096);
            float4* dst = reinterpret_cast<float4*>(sf);
            for (int t = tid; t < 1024; t += 256) dst[t] = src[t];
            __syncthreads();
            curB = b;
        }

        int qi = 4*m2;                                 // xyz2[m2] == xyz1[4*m2]
        float4 q = sp4[qi];

        int kidx = knn16_select<16>(sp4, &dc16[w][0], q.x, q.y, q.z, lane,
                                    &scand[w][0], &sidxs[w][0]);

        // --- full-warp gather into per-warp smem g[16][12] ------------------
        __syncwarp();
        {
            int j = __shfl_sync(FULLM, kidx, lane & 15);
            float* gr = &sg[w][lane & 15][0];
            const float4* fr = reinterpret_cast<const float4*>(sf + j*8);
            if (lane < 16){
                float4 xj = sp4[j];
                float4 f0 = fr[0];
                gr[0]=xj.x-q.x; gr[1]=xj.y-q.y; gr[2]=xj.z-q.z;
                gr[3]=f0.x; gr[4]=f0.y; gr[5]=f0.z; gr[6]=f0.w;
            } else {
                float4 f1 = fr[1];
                gr[7]=f1.x; gr[8]=f1.y; gr[9]=f1.z; gr[10]=f1.w;
            }
        }
        __syncwarp();

        float mx0=-BIGF, mx1=-BIGF, mx2=-BIGF, mx3=-BIGF;
        #pragma unroll 4
        for (int k=0;k<16;k++){
            const float* gr = &sg[w][k][0];
            ulonglong2 pA = *reinterpret_cast<const ulonglong2*>(gr);     // g0..g3
            ulonglong2 pB = *reinterpret_cast<const ulonglong2*>(gr+4);   // g4..g7
            float4     v2 = *reinterpret_cast<const float4*>(gr+8);       // g8..g11(pad)
            unsigned long long p4 = pk(v2.x, v2.y);
            float g10 = v2.z;
            unsigned long long a0=bp0, a1=bp1, a2=bp2, a3=bp3;
            a0 = ffma2(pA.x, wq0[0], a0); a1 = ffma2(pA.x, wq1[0], a1);
            a2 = ffma2(pA.x, wq2[0], a2); a3 = ffma2(pA.x, wq3[0], a3);
            a0 = ffma2(pA.y, wq0[1], a0); a1 = ffma2(pA.y, wq1[1], a1);
            a2 = ffma2(pA.y, wq2[1], a2); a3 = ffma2(pA.y, wq3[1], a3);
            a0 = ffma2(pB.x, wq0[2], a0); a1 = ffma2(pB.x, wq1[2], a1);
            a2 = ffma2(pB.x, wq2[2], a2); a3 = ffma2(pB.x, wq3[2], a3);
            a0 = ffma2(pB.y, wq0[3], a0); a1 = ffma2(pB.y, wq1[3], a1);
            a2 = ffma2(pB.y, wq2[3], a2); a3 = ffma2(pB.y, wq3[3], a3);
            a0 = ffma2(p4,   wq0[4], a0); a1 = ffma2(p4,   wq1[4], a1);
            a2 = ffma2(p4,   wq2[4], a2); a3 = ffma2(p4,   wq3[4], a3);
            float2 s0 = upk(a0), s1 = upk(a1), s2 = upk(a2), s3 = upk(a3);
            float r0 = fmaf(g10, w10_0, s0.x + s0.y);
            float r1 = fmaf(g10, w10_1, s1.x + s1.y);
            float r2 = fmaf(g10, w10_2, s2.x + s2.y);
            float r3 = fmaf(g10, w10_3, s3.x + s3.y);
            mx0 = fmaxf(mx0, lrelu(r0));
            mx1 = fmaxf(mx1, lrelu(r1));
            mx2 = fmaxf(mx2, lrelu(r2));
            mx3 = fmaxf(mx3, lrelu(r3));
        }

        // deterministic per-chunk reduction of the 8 queries' vectors
        sacc[w][lane]      = mx0;
        sacc[w][lane + 32] = mx1;
        sacc[w][lane + 64] = mx2;
        sacc[w][lane + 96] = mx3;
        __syncthreads();
        if (tid < 128){
            float s = sacc[0][tid];
            #pragma unroll
            for (int ww=1; ww<8; ww++) s += sacc[ww][tid];
            g_psum[((size_t)b*16 + chunk)*128 + tid] = s;
        }
        __syncthreads();                                // sacc reuse barrier
    }
}

// ---------------------------------------------------------------------------
// Kernel D: out[b] = (sum of 16 chunk psums)/128 @ We + be
// grid 512, block 128: each block handles one batch half (128 columns).
// ---------------------------------------------------------------------------
__global__ void __launch_bounds__(128) kD(
    const float* __restrict__ We, const float* __restrict__ be,
    float* __restrict__ out)
{
    __shared__ float sbar[128];
    int b   = blockIdx.x >> 1;
    int col = ((blockIdx.x & 1) << 7) + threadIdx.x;
    int tid = threadIdx.x;
    {
        const float* ps = g_psum + (size_t)b*16*128 + tid;
        float s = 0.f;
        #pragma unroll
        for (int k=0;k<16;k++) s += ps[k*128];
        sbar[tid] = s * (1.f/128.f);
    }
    __syncthreads();
    float acc = __ldg(&be[col]);
    #pragma unroll 8
    for (int c=0;c<128;c++) acc = fmaf(sbar[c], __ldg(&We[c*256 + col]), acc);
    out[(size_t)b*256 + col] = acc;
}

// ---------------------------------------------------------------------------
extern "C" void kernel_launch(void* const* d_in, const int* in_sizes, int n_in,
                              void* d_out, int out_size)
{
    (void)in_sizes; (void)n_in; (void)out_size;
    const float* pc  = (const float*)d_in[0];
    const float* W0  = (const float*)d_in[1];
    const float* b0  = (const float*)d_in[2];
    const float* g0  = (const float*)d_in[3];
    const float* be0 = (const float*)d_in[4];
    const float* W1  = (const float*)d_in[5];
    const float* b1  = (const float*)d_in[6];
    const float* g1  = (const float*)d_in[7];
    const float* be1 = (const float*)d_in[8];
    const float* Wp  = (const float*)d_in[9];
    const float* bp  = (const float*)d_in[10];
    const float* Ws  = (const float*)d_in[11];
    const float* bsv = (const float*)d_in[12];
    const float* Wc  = (const float*)d_in[13];
    const float* bc  = (const float*)d_in[14];
    const float* We  = (const float*)d_in[15];
    const float* be  = (const float*)d_in[16];
    float* out = (float*)d_out;

    kA<<<1024, 256>>>(pc, W0, b0, g0, be0, W1, b1, g1, be1);
    kB<<<KB_BLOCKS, 256>>>(pc, Wp, bp, Ws, bsv);
    kC<<<KC_BLOCKS, 256>>>(pc, Wc, bc);
    kD<<<512, 128>>>(We, be, out);
}

// round 15
// speedup vs baseline: 1.0891x; 1.0891x over previous
#include <cuda_runtime.h>
#include <cstdint>

#define FULLM 0xFFFFFFFFu
#define BIGF  3.402823466e+38f

__device__ float g_feat[256*1024*16]; // stage-1 per-point features (B,N,16)
__device__ float g_fs[256*512*8];     // squeezed features on xyz1 (B,512,8)
__device__ float g_psum[256*16*128];  // per-chunk partial sums of f2 (B,16,128)

__device__ __forceinline__ float lrelu(float x){ return x > 0.f ? x : 0.2f*x; }

// ---- packed f32x2 helpers (Blackwell) -------------------------------------
__device__ __forceinline__ unsigned long long pk(float lo, float hi){
    unsigned long long r;
    asm("mov.b64 %0, {%1, %2};" : "=l"(r) : "f"(lo), "f"(hi));
    return r;
}
__device__ __forceinline__ float2 upk(unsigned long long v){
    float2 r;
    asm("mov.b64 {%0, %1}, %2;" : "=f"(r.x), "=f"(r.y) : "l"(v));
    return r;
}
__device__ __forceinline__ unsigned long long ffma2(
    unsigned long long a, unsigned long long b, unsigned long long c){
    unsigned long long d;
    asm("fma.rn.f32x2 %0, %1, %2, %3;" : "=l"(d) : "l"(a), "l"(b), "l"(c));
    return d;
}

__device__ __forceinline__ float qdist(const float4& v, float qx, float qy, float qz){
    // d' = |p|^2 - 2 q.p  (query-constant |q|^2 dropped: order-preserving)
    return fmaf(-2.f, fmaf(qx, v.x, fmaf(qy, v.y, qz*v.z)), v.w);
}

// Value-only bitonic sort of 32 floats across a warp (ascending).
__device__ __forceinline__ float bsort32_val(float s, int lane){
    #pragma unroll
    for (int k = 2; k <= 32; k <<= 1){
        #pragma unroll
        for (int j = k >> 1; j > 0; j >>= 1){
            float o = __shfl_xor_sync(FULLM, s, j);
            bool keepmin = ((lane & j) == 0) == ((lane & k) == 0);
            float mn = fminf(s, o), mx = fmaxf(s, o);
            s = keepmin ? mn : mx;
        }
    }
    return s;
}

// Bitonic sort of 32 (d,i) pairs across a warp, ascending lex (d, then i).
__device__ __forceinline__ void bsort32_pair(float& d, int& i, int lane){
    #pragma unroll
    for (int k = 2; k <= 32; k <<= 1){
        #pragma unroll
        for (int j = k >> 1; j > 0; j >>= 1){
            float od = __shfl_xor_sync(FULLM, d, j);
            int   oi = __shfl_xor_sync(FULLM, i, j);
            bool lower = (lane & j) == 0;
            bool asc   = (lane & k) == 0;
            bool osm   = (od < d) || (od == d && oi < i);
            bool take  = (lower == asc) ? osm : !osm;
            if (take){ d = od; i = oi; }
        }
    }
}

// Exact top-16 of NT*32 candidates. sp holds (x,y,z,|p|^2) per point.
// Returns the set of 16 nearest indices distributed on lanes 0..15
// (arbitrary order — callers only max-pool over the set).
template<int NT>
__device__ __forceinline__ int knn16_select(
    const float4* __restrict__ sp,
    float qx, float qy, float qz, int lane,
    float* scand, int* sidxs)
{
    // --- phase 1: per-lane min distance (4 independent chains) -------------
    float m0 = BIGF, m1 = BIGF, m2 = BIGF, m3 = BIGF;
    #pragma unroll
    for (int t = 0; t < NT; t += 4){
        float d0 = qdist(sp[lane + (t  )*32], qx, qy, qz);
        float d1 = qdist(sp[lane + (t+1)*32], qx, qy, qz);
        float d2 = qdist(sp[lane + (t+2)*32], qx, qy, qz);
        float d3 = qdist(sp[lane + (t+3)*32], qx, qy, qz);
        m0 = fminf(m0, d0); m1 = fminf(m1, d1);
        m2 = fminf(m2, d2); m3 = fminf(m3, d3);
    }
    float bd = fminf(fminf(m0, m1), fminf(m2, m3));

    // --- phase 2: threshold = 16th-smallest lane minimum (valid bound) -----
    float thr = __shfl_sync(FULLM, bsort32_val(bd, lane), 15);

    // --- phase 3: bitmask compaction of all d <= thr (no ballots) ----------
    unsigned qmask = 0;
    #pragma unroll
    for (int t = 0; t < NT; t++){
        float d = qdist(sp[lane + t*32], qx, qy, qz);
        if (d <= thr) qmask |= (1u << t);
    }
    int myc = __popc(qmask);
    // inclusive shfl scan -> exclusive offset + warp total
    int off = myc;
    #pragma unroll
    for (int s = 1; s < 32; s <<= 1){
        int o = __shfl_up_sync(FULLM, off, s);
        if (lane >= s) off += o;
    }
    int cnt = __shfl_sync(FULLM, off, 31);
    off -= myc;

    scand[lane] = BIGF; sidxs[lane] = 0x7FFFFFFF;
    __syncwarp();
    {
        unsigned mm = qmask;
        int pos = off;
        while (mm){
            int t = __ffs(mm) - 1;
            mm &= mm - 1;
            if (pos < 32){
                float d = qdist(sp[lane + t*32], qx, qy, qz);
                scand[pos] = d; sidxs[pos] = lane + t*32;
            }
            pos++;
        }
    }
    __syncwarp();

    int kidx;
    if (cnt <= 32){
        float d2 = scand[lane]; int i2 = sidxs[lane];
        // value-only sort to find the 16th-smallest distance in the buffer
        float thr16 = __shfl_sync(FULLM, bsort32_val(d2, lane), 15);
        unsigned lt = (1u << lane) - 1u;
        unsigned sel = __ballot_sync(FULLM, d2 <= thr16);
        if (__popc(sel) == 16){
            // no boundary tie: selected lanes ARE the exact top-16 set
            __syncwarp();
            if (d2 <= thr16){
                int pos = __popc(sel & lt);
                sidxs[pos] = i2;
            }
            __syncwarp();
            kidx = sidxs[lane & 15];
        } else {
            // boundary tie on distance: exact lex (d, idx) sort
            bsort32_pair(d2, i2, lane);
            kidx = i2;
        }
    } else {
        // --- rare fallback: progressive argmin with lex exclusion ----------
        float lastD = -BIGF; int lastI = -1; kidx = 0x7FFFFFFF;
        for (int r = 0; r < 16; r++){
            float cbd = BIGF; int cbi = 0x7FFFFFFF;
            #pragma unroll
            for (int t = 0; t < NT; t++){
                int j = lane + t*32;
                float d = qdist(sp[j], qx, qy, qz);
                bool gt = (d > lastD) || (d == lastD && j > lastI);
                if (gt && ((d < cbd) || (d == cbd && j < cbi))){ cbd = d; cbi = j; }
            }
            #pragma unroll
            for (int off2 = 16; off2 > 0; off2 >>= 1){
                float od = __shfl_down_sync(FULLM, cbd, off2);
                int   oi = __shfl_down_sync(FULLM, cbi, off2);
                if (od < cbd || (od == cbd && oi < cbi)){ cbd = od; cbi = oi; }
            }
            lastD = __shfl_sync(FULLM, cbd, 0);
            lastI = __shfl_sync(FULLM, cbi, 0);
            if (lane == r) kidx = lastI;
        }
    }
    return kidx;
}

// ---------------------------------------------------------------------------
// Kernel A: f = lrelu(LN(lrelu(LN(xyz@W0+b0))@W1+b1))  per point.
// Weight loads vectorized to float4 (arithmetic order unchanged).
// ---------------------------------------------------------------------------
__global__ void __launch_bounds__(256) kA(
    const float* __restrict__ pc,
    const float* __restrict__ W0, const float* __restrict__ b0,
    const float* __restrict__ g0, const float* __restrict__ be0,
    const float* __restrict__ W1, const float* __restrict__ b1,
    const float* __restrict__ g1, const float* __restrict__ be1)
{
    int i = blockIdx.x*256 + threadIdx.x;
    int b = i >> 10, n = i & 1023;
    const float* p = pc + (size_t)b*3072;
    float x = p[n], y = p[1024+n], z = p[2048+n];

    const float4* W0_4  = reinterpret_cast<const float4*>(W0);
    const float4* b0_4  = reinterpret_cast<const float4*>(b0);
    const float4* g0_4  = reinterpret_cast<const float4*>(g0);
    const float4* be0_4 = reinterpret_cast<const float4*>(be0);
    const float4* b1_4  = reinterpret_cast<const float4*>(b1);
    const float4* g1_4  = reinterpret_cast<const float4*>(g1);
    const float4* be1_4 = reinterpret_cast<const float4*>(be1);

    float t[16];
    #pragma unroll
    for (int g=0; g<4; g++){
        float4 w0r = __ldg(&W0_4[g]);
        float4 w1r = __ldg(&W0_4[4+g]);
        float4 w2r = __ldg(&W0_4[8+g]);
        float4 bb  = __ldg(&b0_4[g]);
        t[4*g+0] = fmaf(x, w0r.x, fmaf(y, w1r.x, fmaf(z, w2r.x, bb.x)));
        t[4*g+1] = fmaf(x, w0r.y, fmaf(y, w1r.y, fmaf(z, w2r.y, bb.y)));
        t[4*g+2] = fmaf(x, w0r.z, fmaf(y, w1r.z, fmaf(z, w2r.z, bb.z)));
        t[4*g+3] = fmaf(x, w0r.w, fmaf(y, w1r.w, fmaf(z, w2r.w, bb.w)));
    }
    {
        float m=0.f;
        #pragma unroll
        for (int c=0;c<16;c++) m += t[c];
        m *= (1.f/16.f);
        float v=0.f;
        #pragma unroll
        for (int c=0;c<16;c++){ float dd=t[c]-m; v = fmaf(dd,dd,v); }
        v *= (1.f/16.f);
        float inv = rsqrtf(v + 1e-5f);
        #pragma unroll
        for (int g=0; g<4; g++){
            float4 gg = __ldg(&g0_4[g]);
            float4 bb = __ldg(&be0_4[g]);
            t[4*g+0] = lrelu(fmaf((t[4*g+0]-m)*inv, gg.x, bb.x));
            t[4*g+1] = lrelu(fmaf((t[4*g+1]-m)*inv, gg.y, bb.y));
            t[4*g+2] = lrelu(fmaf((t[4*g+2]-m)*inv, gg.z, bb.z));
            t[4*g+3] = lrelu(fmaf((t[4*g+3]-m)*inv, gg.w, bb.w));
        }
    }
    float4 acc0 = __ldg(&b1_4[0]);
    float4 acc1 = __ldg(&b1_4[1]);
    float4 acc2 = __ldg(&b1_4[2]);
    float4 acc3 = __ldg(&b1_4[3]);
    #pragma unroll
    for (int c=0;c<16;c++){
        float tc = t[c];
        const float4* wr = reinterpret_cast<const float4*>(W1 + c*16);
        float4 w0v = __ldg(&wr[0]);
        float4 w1v = __ldg(&wr[1]);
        float4 w2v = __ldg(&wr[2]);
        float4 w3v = __ldg(&wr[3]);
        acc0.x = fmaf(tc, w0v.x, acc0.x); acc0.y = fmaf(tc, w0v.y, acc0.y);
        acc0.z = fmaf(tc, w0v.z, acc0.z); acc0.w = fmaf(tc, w0v.w, acc0.w);
        acc1.x = fmaf(tc, w1v.x, acc1.x); acc1.y = fmaf(tc, w1v.y, acc1.y);
        acc1.z = fmaf(tc, w1v.z, acc1.z); acc1.w = fmaf(tc, w1v.w, acc1.w);
        acc2.x = fmaf(tc, w2v.x, acc2.x); acc2.y = fmaf(tc, w2v.y, acc2.y);
        acc2.z = fmaf(tc, w2v.z, acc2.z); acc2.w = fmaf(tc, w2v.w, acc2.w);
        acc3.x = fmaf(tc, w3v.x, acc3.x); acc3.y = fmaf(tc, w3v.y, acc3.y);
        acc3.z = fmaf(tc, w3v.z, acc3.z); acc3.w = fmaf(tc, w3v.w, acc3.w);
    }
    float u[16] = {acc0.x,acc0.y,acc0.z,acc0.w, acc1.x,acc1.y,acc1.z,acc1.w,
                   acc2.x,acc2.y,acc2.z,acc2.w, acc3.x,acc3.y,acc3.z,acc3.w};
    {
        float m=0.f;
        #pragma unroll
        for (int c=0;c<16;c++) m += u[c];
        m *= (1.f/16.f);
        float v=0.f;
        #pragma unroll
        for (int c=0;c<16;c++){ float dd=u[c]-m; v = fmaf(dd,dd,v); }
        v *= (1.f/16.f);
        float inv = rsqrtf(v + 1e-5f);
        #pragma unroll
        for (int g=0; g<4; g++){
            float4 gg = __ldg(&g1_4[g]);
            float4 bb = __ldg(&be1_4[g]);
            u[4*g+0] = lrelu(fmaf((u[4*g+0]-m)*inv, gg.x, bb.x));
            u[4*g+1] = lrelu(fmaf((u[4*g+1]-m)*inv, gg.y, bb.y));
            u[4*g+2] = lrelu(fmaf((u[4*g+2]-m)*inv, gg.z, bb.z));
            u[4*g+3] = lrelu(fmaf((u[4*g+3]-m)*inv, gg.w, bb.w));
        }
    }
    float4* o4 = reinterpret_cast<float4*>(g_feat + (size_t)i*16);
    o4[0] = make_float4(u[0],u[1],u[2],u[3]);
    o4[1] = make_float4(u[4],u[5],u[6],u[7]);
    o4[2] = make_float4(u[8],u[9],u[10],u[11]);
    o4[3] = make_float4(u[12],u[13],u[14],u[15]);
}

// ---------------------------------------------------------------------------
// Kernel B: pointconv1 (K=16 NN of 512 queries over 1024 pts) + fused squeeze
// Persistent grid of 444 blocks (148 SMs x occ 3). 16384 chunks of 8 queries;
// contiguous runs of 36/37 chunks per block.
// ---------------------------------------------------------------------------
#define KB_BLOCKS 444

__global__ void __launch_bounds__(256, 3) kB(
    const float* __restrict__ pc,
    const float* __restrict__ Wp, const float* __restrict__ bp,
    const float* __restrict__ Ws, const float* __restrict__ bsv)
{
    __shared__ __align__(16) float4 sp4[1024];
    __shared__ __align__(16) float  sg[8][16][20];
    __shared__ __align__(16) float  scand[8][32];
    __shared__ __align__(16) int    sidxs[8][32];
    __shared__ __align__(16) float  smx[8][32];

    int tid  = threadIdx.x;
    int lane = tid & 31;
    int w    = tid >> 5;
    int bid  = blockIdx.x;

    // contiguous chunk partition: 16384 = 400*37 + 44*36
    int start, cnt;
    if (bid < 400){ start = bid*37;               cnt = 37; }
    else          { start = 14800 + (bid-400)*36; cnt = 36; }

    // packed per-lane GEMM weights: lane = output channel
    unsigned long long wp[9];
    #pragma unroll
    for (int c=0;c<9;c++)
        wp[c] = pk(__ldg(&Wp[(2*c)*32 + lane]), __ldg(&Wp[(2*c+1)*32 + lane]));
    float wr18 = __ldg(&Wp[18*32 + lane]);
    unsigned long long accp = pk(__ldg(&bp[lane]), 0.f);

    // squeeze weights: lane handles output j = lane&7 over c in [cb, cb+8)
    int jq = lane & 7, cb = (lane >> 3) * 8;
    unsigned long long wsp[4];
    #pragma unroll
    for (int i=0;i<4;i++)
        wsp[i] = pk(__ldg(&Ws[(cb+2*i)*8 + jq]), __ldg(&Ws[(cb+2*i+1)*8 + jq]));
    float bsq = __ldg(&bsv[jq]);

    int curB = -1;
    for (int ci = start; ci < start + cnt; ci++){
        int b    = ci >> 6;
        int m    = ((ci & 63) << 3) + w;              // this warp's query
        if (b != curB){
            __syncthreads();                           // old sp4 fully consumed
            const float* p = pc + (size_t)b*3072;
            for (int n = tid; n < 1024; n += 256){
                float X = p[n], Y = p[1024+n], Z = p[2048+n];
                sp4[n] = make_float4(X, Y, Z, fmaf(X,X, fmaf(Y,Y, Z*Z)));
            }
            __syncthreads();
            curB = b;
        }

        int qi = 2*m;                                  // xyz1[m] == xyz0[2m]
        float4 q = sp4[qi];

        int kidx = knn16_select<32>(sp4, q.x, q.y, q.z, lane,
                                    &scand[w][0], &sidxs[w][0]);

        // --- full-warp gather into per-warp smem g[16][20] ------------------
        __syncwarp();
        {
            int j = __shfl_sync(FULLM, kidx, lane & 15);
            float* gr = &sg[w][lane & 15][0];
            const float4* fr = reinterpret_cast<const float4*>(
                g_feat + ((size_t)b*1024 + j)*16);
            if (lane < 16){
                float4 xj = sp4[j];
                float4 f0 = fr[0], f1 = fr[1];
                gr[0]=xj.x-q.x; gr[1]=xj.y-q.y; gr[2]=xj.z-q.z;
                gr[3]=f0.x;  gr[4]=f0.y;  gr[5]=f0.z;  gr[6]=f0.w;
                gr[7]=f1.x;  gr[8]=f1.y;  gr[9]=f1.z;  gr[10]=f1.w;
            } else {
                float4 f2v = fr[2], f3 = fr[3];
                gr[11]=f2v.x; gr[12]=f2v.y; gr[13]=f2v.z; gr[14]=f2v.w;
                gr[15]=f3.x;  gr[16]=f3.y;  gr[17]=f3.z;  gr[18]=f3.w;
            }
        }
        __syncwarp();

        // --- GEMM (lane = output channel) via packed FFMA2 + maxpool -------
        float mx = -BIGF;
        #pragma unroll 4
        for (int k=0;k<16;k++){
            const float* gr = &sg[w][k][0];
            ulonglong2 pA = *reinterpret_cast<const ulonglong2*>(gr);
            ulonglong2 pB = *reinterpret_cast<const ulonglong2*>(gr+4);
            ulonglong2 pC = *reinterpret_cast<const ulonglong2*>(gr+8);
            ulonglong2 pD = *reinterpret_cast<const ulonglong2*>(gr+12);
            unsigned long long pE = *reinterpret_cast<const unsigned long long*>(gr+16);
            float  g18 = gr[18];
            unsigned long long acc = accp;
            acc = ffma2(pA.x, wp[0], acc);
            acc = ffma2(pA.y, wp[1], acc);
            acc = ffma2(pB.x, wp[2], acc);
            acc = ffma2(pB.y, wp[3], acc);
            acc = ffma2(pC.x, wp[4], acc);
            acc = ffma2(pC.y, wp[5], acc);
            acc = ffma2(pD.x, wp[6], acc);
            acc = ffma2(pD.y, wp[7], acc);
            acc = ffma2(pE,   wp[8], acc);
            float2 s = upk(acc);
            float a = fmaf(g18, wr18, s.x + s.y);
            mx = fmaxf(mx, lrelu(a));
        }

        // --- fused squeeze via smem transpose: fs = lrelu(mx @ Ws + bs) -----
        smx[w][lane] = mx;
        __syncwarp();
        const unsigned long long* mp =
            reinterpret_cast<const unsigned long long*>(&smx[w][cb]);
        unsigned long long s2 = pk(0.f, 0.f);
        s2 = ffma2(mp[0], wsp[0], s2);
        s2 = ffma2(mp[1], wsp[1], s2);
        s2 = ffma2(mp[2], wsp[2], s2);
        s2 = ffma2(mp[3], wsp[3], s2);
        float2 sv = upk(s2);
        float s = sv.x + sv.y;
        s += __shfl_down_sync(FULLM, s, 16);
        s += __shfl_down_sync(FULLM, s, 8);
        if (lane < 8)
            g_fs[((size_t)b*512 + m)*8 + jq] = lrelu(s + bsq);
    }
}

// ---------------------------------------------------------------------------
// Kernel C: pointconv2 (128 queries, 512 candidates, 11ch -> 128ch) with
// fused per-chunk column-sum. Persistent grid of 444 blocks; 4096 chunks of
// 8 queries (16 chunks/batch), contiguous runs of 9/10 chunks per block.
// ---------------------------------------------------------------------------
#define KC_BLOCKS 444

__global__ void __launch_bounds__(256, 3) kC(
    const float* __restrict__ pc,
    const float* __restrict__ Wc, const float* __restrict__ bc)
{
    __shared__ __align__(16) float4 sp4[512];
    __shared__ __align__(16) float  sf[512*8];
    __shared__ __align__(16) float  sg[8][16][12];
    __shared__ __align__(16) float  scand[8][32];
    __shared__ __align__(16) int    sidxs[8][32];
    __shared__ float  sacc[8][128];

    int tid  = threadIdx.x;
    int lane = tid & 31;
    int w    = tid >> 5;
    int bid  = blockIdx.x;

    // contiguous chunk partition: 4096 = 100*10 + 344*9
    int start, cnt;
    if (bid < 100){ start = bid*10;              cnt = 10; }
    else          { start = 1000 + (bid-100)*9;  cnt = 9;  }

    // packed weights for 4 output channels per lane (lane, lane+32, +64, +96)
    unsigned long long wq0[5], wq1[5], wq2[5], wq3[5];
    #pragma unroll
    for (int c=0;c<5;c++){
        wq0[c] = pk(__ldg(&Wc[(2*c)*128 + lane]),      __ldg(&Wc[(2*c+1)*128 + lane]));
        wq1[c] = pk(__ldg(&Wc[(2*c)*128 + lane + 32]), __ldg(&Wc[(2*c+1)*128 + lane + 32]));
        wq2[c] = pk(__ldg(&Wc[(2*c)*128 + lane + 64]), __ldg(&Wc[(2*c+1)*128 + lane + 64]));
        wq3[c] = pk(__ldg(&Wc[(2*c)*128 + lane + 96]), __ldg(&Wc[(2*c+1)*128 + lane + 96]));
    }
    float w10_0 = __ldg(&Wc[10*128 + lane]),      w10_1 = __ldg(&Wc[10*128 + lane + 32]);
    float w10_2 = __ldg(&Wc[10*128 + lane + 64]), w10_3 = __ldg(&Wc[10*128 + lane + 96]);
    unsigned long long bp0 = pk(__ldg(&bc[lane]),     0.f);
    unsigned long long bp1 = pk(__ldg(&bc[lane+32]),  0.f);
    unsigned long long bp2 = pk(__ldg(&bc[lane+64]),  0.f);
    unsigned long long bp3 = pk(__ldg(&bc[lane+96]),  0.f);

    int curB = -1;
    for (int ci = start; ci < start + cnt; ci++){
        int b     = ci >> 4;
        int chunk = ci & 15;
        int m2    = (chunk << 3) + w;                 // this warp's query
        if (b != curB){
            __syncthreads();                           // old sp4/sf consumed
            const float* p = pc + (size_t)b*3072;
            for (int m = tid; m < 512; m += 256){
                float X = p[2*m], Y = p[1024+2*m], Z = p[2048+2*m];
                sp4[m] = make_float4(X, Y, Z, fmaf(X,X, fmaf(Y,Y, Z*Z)));
            }
            const float4* src = reinterpret_cast<const float4*>(g_fs + (size_t)b*4096);
            float4* dst = reinterpret_cast<float4*>(sf);
            for (int t = tid; t < 1024; t += 256) dst[t] = src[t];
            __syncthreads();
            curB = b;
        }

        int qi = 4*m2;                                 // xyz2[m2] == xyz1[4*m2]
        float4 q = sp4[qi];

        int kidx = knn16_select<16>(sp4, q.x, q.y, q.z, lane,
                                    &scand[w][0], &sidxs[w][0]);

        // --- full-warp gather into per-warp smem g[16][12] ------------------
        __syncwarp();
        {
            int j = __shfl_sync(FULLM, kidx, lane & 15);
            float* gr = &sg[w][lane & 15][0];
            const float4* fr = reinterpret_cast<const float4*>(sf + j*8);
            if (lane < 16){
                float4 xj = sp4[j];
                float4 f0 = fr[0];
                gr[0]=xj.x-q.x; gr[1]=xj.y-q.y; gr[2]=xj.z-q.z;
                gr[3]=f0.x; gr[4]=f0.y; gr[5]=f0.z; gr[6]=f0.w;
            } else {
                float4 f1 = fr[1];
                gr[7]=f1.x; gr[8]=f1.y; gr[9]=f1.z; gr[10]=f1.w;
            }
        }
        __syncwarp();

        float mx0=-BIGF, mx1=-BIGF, mx2=-BIGF, mx3=-BIGF;
        #pragma unroll 4
        for (int k=0;k<16;k++){
            const float* gr = &sg[w][k][0];
            ulonglong2 pA = *reinterpret_cast<const ulonglong2*>(gr);     // g0..g3
            ulonglong2 pB = *reinterpret_cast<const ulonglong2*>(gr+4);   // g4..g7
            float4     v2 = *reinterpret_cast<const float4*>(gr+8);       // g8..g11(pad)
            unsigned long long p4 = pk(v2.x, v2.y);
            float g10 = v2.z;
            unsigned long long a0=bp0, a1=bp1, a2=bp2, a3=bp3;
            a0 = ffma2(pA.x, wq0[0], a0); a1 = ffma2(pA.x, wq1[0], a1);
            a2 = ffma2(pA.x, wq2[0], a2); a3 = ffma2(pA.x, wq3[0], a3);
            a0 = ffma2(pA.y, wq0[1], a0); a1 = ffma2(pA.y, wq1[1], a1);
            a2 = ffma2(pA.y, wq2[1], a2); a3 = ffma2(pA.y, wq3[1], a3);
            a0 = ffma2(pB.x, wq0[2], a0); a1 = ffma2(pB.x, wq1[2], a1);
            a2 = ffma2(pB.x, wq2[2], a2); a3 = ffma2(pB.x, wq3[2], a3);
            a0 = ffma2(pB.y, wq0[3], a0); a1 = ffma2(pB.y, wq1[3], a1);
            a2 = ffma2(pB.y, wq2[3], a2); a3 = ffma2(pB.y, wq3[3], a3);
            a0 = ffma2(p4,   wq0[4], a0); a1 = ffma2(p4,   wq1[4], a1);
            a2 = ffma2(p4,   wq2[4], a2); a3 = ffma2(p4,   wq3[4], a3);
            float2 s0 = upk(a0), s1 = upk(a1), s2 = upk(a2), s3 = upk(a3);
            float r0 = fmaf(g10, w10_0, s0.x + s0.y);
            float r1 = fmaf(g10, w10_1, s1.x + s1.y);
            float r2 = fmaf(g10, w10_2, s2.x + s2.y);
            float r3 = fmaf(g10, w10_3, s3.x + s3.y);
            mx0 = fmaxf(mx0, lrelu(r0));
            mx1 = fmaxf(mx1, lrelu(r1));
            mx2 = fmaxf(mx2, lrelu(r2));
            mx3 = fmaxf(mx3, lrelu(r3));
        }

        // deterministic per-chunk reduction of the 8 queries' vectors
        sacc[w][lane]      = mx0;
        sacc[w][lane + 32] = mx1;
        sacc[w][lane + 64] = mx2;
        sacc[w][lane + 96] = mx3;
        __syncthreads();
        if (tid < 128){
            float s = sacc[0][tid];
            #pragma unroll
            for (int ww=1; ww<8; ww++) s += sacc[ww][tid];
            g_psum[((size_t)b*16 + chunk)*128 + tid] = s;
        }
        __syncthreads();                                // sacc reuse barrier
    }
}

// ---------------------------------------------------------------------------
// Kernel D: out[b] = (sum of 16 chunk psums)/128 @ We + be
// (R12 shape: one block per batch — measured faster than the split variant)
// ---------------------------------------------------------------------------
__global__ void __launch_bounds__(256) kD(
    const float* __restrict__ We, const float* __restrict__ be,
    float* __restrict__ out)
{
    __shared__ float sbar[128];
    int b = blockIdx.x, tid = threadIdx.x;
    if (tid < 128){
        const float* ps = g_psum + (size_t)b*16*128 + tid;
        float s = 0.f;
        #pragma unroll
        for (int k=0;k<16;k++) s += ps[k*128];
        sbar[tid] = s * (1.f/128.f);
    }
    __syncthreads();
    float acc = __ldg(&be[tid]);
    #pragma unroll 8
    for (int c=0;c<128;c++) acc = fmaf(sbar[c], __ldg(&We[c*256 + tid]), acc);
    out[(size_t)b*256 + tid] = acc;
}

// ---------------------------------------------------------------------------
extern "C" void kernel_launch(void* const* d_in, const int* in_sizes, int n_in,
                              void* d_out, int out_size)
{
    (void)in_sizes; (void)n_in; (void)out_size;
    const float* pc  = (const float*)d_in[0];
    const float* W0  = (const float*)d_in[1];
    const float* b0  = (const float*)d_in[2];
    const float* g0  = (const float*)d_in[3];
    const float* be0 = (const float*)d_in[4];
    const float* W1  = (const float*)d_in[5];
    const float* b1  = (const float*)d_in[6];
    const float* g1  = (const float*)d_in[7];
    const float* be1 = (const float*)d_in[8];
    const float* Wp  = (const float*)d_in[9];
    const float* bp  = (const float*)d_in[10];
    const float* Ws  = (const float*)d_in[11];
    const float* bsv = (const float*)d_in[12];
    const float* Wc  = (const float*)d_in[13];
    const float* bc  = (const float*)d_in[14];
    const float* We  = (const float*)d_in[15];
    const float* be  = (const float*)d_in[16];
    float* out = (float*)d_out;

    kA<<<1024, 256>>>(pc, W0, b0, g0, be0, W1, b1, g1, be1);
    kB<<<KB_BLOCKS, 256>>>(pc, Wp, bp, Ws, bsv);
    kC<<<KC_BLOCKS, 256>>>(pc, Wc, bc);
    kD<<<256, 256>>>(We, be, out);
}

// round 16
// speedup vs baseline: 1.1030x; 1.0128x over previous
#include <cuda_runtime.h>
#include <cstdint>

#define FULLM 0xFFFFFFFFu
#define BIGF  3.402823466e+38f

__device__ float g_feat[256*1024*16]; // stage-1 per-point features (B,N,16)
__device__ float g_fs[256*512*8];     // squeezed features on xyz1 (B,512,8)
__device__ float g_psum[256*16*128];  // per-chunk partial sums of f2 (B,16,128)

__device__ __forceinline__ float lrelu(float x){ return x > 0.f ? x : 0.2f*x; }

// ---- packed f32x2 helpers (Blackwell) -------------------------------------
__device__ __forceinline__ unsigned long long pk(float lo, float hi){
    unsigned long long r;
    asm("mov.b64 %0, {%1, %2};" : "=l"(r) : "f"(lo), "f"(hi));
    return r;
}
__device__ __forceinline__ float2 upk(unsigned long long v){
    float2 r;
    asm("mov.b64 {%0, %1}, %2;" : "=f"(r.x), "=f"(r.y) : "l"(v));
    return r;
}
__device__ __forceinline__ unsigned long long ffma2(
    unsigned long long a, unsigned long long b, unsigned long long c){
    unsigned long long d;
    asm("fma.rn.f32x2 %0, %1, %2, %3;" : "=l"(d) : "l"(a), "l"(b), "l"(c));
    return d;
}

__device__ __forceinline__ float qdist(const float4& v, float qx, float qy, float qz){
    // d' = |p|^2 - 2 q.p  (query-constant |q|^2 dropped: order-preserving)
    return fmaf(-2.f, fmaf(qx, v.x, fmaf(qy, v.y, qz*v.z)), v.w);
}

// Value-only bitonic sort of 32 floats across a warp (ascending).
__device__ __forceinline__ float bsort32_val(float s, int lane){
    #pragma unroll
    for (int k = 2; k <= 32; k <<= 1){
        #pragma unroll
        for (int j = k >> 1; j > 0; j >>= 1){
            float o = __shfl_xor_sync(FULLM, s, j);
            bool keepmin = ((lane & j) == 0) == ((lane & k) == 0);
            float mn = fminf(s, o), mx = fmaxf(s, o);
            s = keepmin ? mn : mx;
        }
    }
    return s;
}

// Bitonic sort of 32 (d,i) pairs across a warp, ascending lex (d, then i).
__device__ __forceinline__ void bsort32_pair(float& d, int& i, int lane){
    #pragma unroll
    for (int k = 2; k <= 32; k <<= 1){
        #pragma unroll
        for (int j = k >> 1; j > 0; j >>= 1){
            float od = __shfl_xor_sync(FULLM, d, j);
            int   oi = __shfl_xor_sync(FULLM, i, j);
            bool lower = (lane & j) == 0;
            bool asc   = (lane & k) == 0;
            bool osm   = (od < d) || (od == d && oi < i);
            bool take  = (lower == asc) ? osm : !osm;
            if (take){ d = od; i = oi; }
        }
    }
}

// Exact top-16 of NT*32 candidates. sp holds (x,y,z,|p|^2) per point.
// Returns the set of 16 nearest indices distributed on lanes 0..15
// (arbitrary order — callers only max-pool over the set).
// Phase-3 buffer stores INDICES only; phase 4 recomputes the (bit-identical)
// distance once per lane — cheaper than storing (d,idx) pairs in the
// divergent write-out loop.
template<int NT>
__device__ __forceinline__ int knn16_select(
    const float4* __restrict__ sp,
    float qx, float qy, float qz, int lane,
    int* sidxs)
{
    // --- phase 1: per-lane min distance (4 independent chains) -------------
    float m0 = BIGF, m1 = BIGF, m2 = BIGF, m3 = BIGF;
    #pragma unroll
    for (int t = 0; t < NT; t += 4){
        float d0 = qdist(sp[lane + (t  )*32], qx, qy, qz);
        float d1 = qdist(sp[lane + (t+1)*32], qx, qy, qz);
        float d2 = qdist(sp[lane + (t+2)*32], qx, qy, qz);
        float d3 = qdist(sp[lane + (t+3)*32], qx, qy, qz);
        m0 = fminf(m0, d0); m1 = fminf(m1, d1);
        m2 = fminf(m2, d2); m3 = fminf(m3, d3);
    }
    float bd = fminf(fminf(m0, m1), fminf(m2, m3));

    // --- phase 2: threshold = 16th-smallest lane minimum (valid bound) -----
    float thr = __shfl_sync(FULLM, bsort32_val(bd, lane), 15);

    // --- phase 3: bitmask compaction of all d <= thr (indices only) --------
    unsigned qmask = 0;
    #pragma unroll
    for (int t = 0; t < NT; t++){
        float d = qdist(sp[lane + t*32], qx, qy, qz);
        if (d <= thr) qmask |= (1u << t);
    }
    int myc = __popc(qmask);
    // inclusive shfl scan -> exclusive offset + warp total
    int off = myc;
    #pragma unroll
    for (int s = 1; s < 32; s <<= 1){
        int o = __shfl_up_sync(FULLM, off, s);
        if (lane >= s) off += o;
    }
    int cnt = __shfl_sync(FULLM, off, 31);
    off -= myc;

    sidxs[lane] = 0x7FFFFFFF;
    __syncwarp();
    {
        unsigned mm = qmask;
        int pos = off;
        while (mm){
            int t = __ffs(mm) - 1;
            mm &= mm - 1;
            if (pos < 32) sidxs[pos] = lane + t*32;
            pos++;
        }
    }
    __syncwarp();

    int kidx;
    if (cnt <= 32){
        int i2 = sidxs[lane];
        float d2 = (i2 != 0x7FFFFFFF) ? qdist(sp[i2], qx, qy, qz) : BIGF;
        // value-only sort to find the 16th-smallest distance in the buffer
        float thr16 = __shfl_sync(FULLM, bsort32_val(d2, lane), 15);
        unsigned lt = (1u << lane) - 1u;
        unsigned sel = __ballot_sync(FULLM, d2 <= thr16);
        if (__popc(sel) == 16){
            // no boundary tie: selected lanes ARE the exact top-16 set
            __syncwarp();
            if (d2 <= thr16){
                int pos = __popc(sel & lt);
                sidxs[pos] = i2;
            }
            __syncwarp();
            kidx = sidxs[lane & 15];
        } else {
            // boundary tie on distance: exact lex (d, idx) sort
            bsort32_pair(d2, i2, lane);
            kidx = i2;
        }
    } else {
        // --- rare fallback: progressive argmin with lex exclusion ----------
        float lastD = -BIGF; int lastI = -1; kidx = 0x7FFFFFFF;
        for (int r = 0; r < 16; r++){
            float cbd = BIGF; int cbi = 0x7FFFFFFF;
            #pragma unroll
            for (int t = 0; t < NT; t++){
                int j = lane + t*32;
                float d = qdist(sp[j], qx, qy, qz);
                bool gt = (d > lastD) || (d == lastD && j > lastI);
                if (gt && ((d < cbd) || (d == cbd && j < cbi))){ cbd = d; cbi = j; }
            }
            #pragma unroll
            for (int off2 = 16; off2 > 0; off2 >>= 1){
                float od = __shfl_down_sync(FULLM, cbd, off2);
                int   oi = __shfl_down_sync(FULLM, cbi, off2);
                if (od < cbd || (od == cbd && oi < cbi)){ cbd = od; cbi = oi; }
            }
            lastD = __shfl_sync(FULLM, cbd, 0);
            lastI = __shfl_sync(FULLM, cbi, 0);
            if (lane == r) kidx = lastI;
        }
    }
    return kidx;
}

// ---------------------------------------------------------------------------
// Kernel A: f = lrelu(LN(lrelu(LN(xyz@W0+b0))@W1+b1))  per point.
// Weight loads vectorized to float4 (arithmetic order unchanged).
// ---------------------------------------------------------------------------
__global__ void __launch_bounds__(256) kA(
    const float* __restrict__ pc,
    const float* __restrict__ W0, const float* __restrict__ b0,
    const float* __restrict__ g0, const float* __restrict__ be0,
    const float* __restrict__ W1, const float* __restrict__ b1,
    const float* __restrict__ g1, const float* __restrict__ be1)
{
    int i = blockIdx.x*256 + threadIdx.x;
    int b = i >> 10, n = i & 1023;
    const float* p = pc + (size_t)b*3072;
    float x = p[n], y = p[1024+n], z = p[2048+n];

    const float4* W0_4  = reinterpret_cast<const float4*>(W0);
    const float4* b0_4  = reinterpret_cast<const float4*>(b0);
    const float4* g0_4  = reinterpret_cast<const float4*>(g0);
    const float4* be0_4 = reinterpret_cast<const float4*>(be0);
    const float4* b1_4  = reinterpret_cast<const float4*>(b1);
    const float4* g1_4  = reinterpret_cast<const float4*>(g1);
    const float4* be1_4 = reinterpret_cast<const float4*>(be1);

    float t[16];
    #pragma unroll
    for (int g=0; g<4; g++){
        float4 w0r = __ldg(&W0_4[g]);
        float4 w1r = __ldg(&W0_4[4+g]);
        float4 w2r = __ldg(&W0_4[8+g]);
        float4 bb  = __ldg(&b0_4[g]);
        t[4*g+0] = fmaf(x, w0r.x, fmaf(y, w1r.x, fmaf(z, w2r.x, bb.x)));
        t[4*g+1] = fmaf(x, w0r.y, fmaf(y, w1r.y, fmaf(z, w2r.y, bb.y)));
        t[4*g+2] = fmaf(x, w0r.z, fmaf(y, w1r.z, fmaf(z, w2r.z, bb.z)));
        t[4*g+3] = fmaf(x, w0r.w, fmaf(y, w1r.w, fmaf(z, w2r.w, bb.w)));
    }
    {
        float m=0.f;
        #pragma unroll
        for (int c=0;c<16;c++) m += t[c];
        m *= (1.f/16.f);
        float v=0.f;
        #pragma unroll
        for (int c=0;c<16;c++){ float dd=t[c]-m; v = fmaf(dd,dd,v); }
        v *= (1.f/16.f);
        float inv = rsqrtf(v + 1e-5f);
        #pragma unroll
        for (int g=0; g<4; g++){
            float4 gg = __ldg(&g0_4[g]);
            float4 bb = __ldg(&be0_4[g]);
            t[4*g+0] = lrelu(fmaf((t[4*g+0]-m)*inv, gg.x, bb.x));
            t[4*g+1] = lrelu(fmaf((t[4*g+1]-m)*inv, gg.y, bb.y));
            t[4*g+2] = lrelu(fmaf((t[4*g+2]-m)*inv, gg.z, bb.z));
            t[4*g+3] = lrelu(fmaf((t[4*g+3]-m)*inv, gg.w, bb.w));
        }
    }
    float4 acc0 = __ldg(&b1_4[0]);
    float4 acc1 = __ldg(&b1_4[1]);
    float4 acc2 = __ldg(&b1_4[2]);
    float4 acc3 = __ldg(&b1_4[3]);
    #pragma unroll
    for (int c=0;c<16;c++){
        float tc = t[c];
        const float4* wr = reinterpret_cast<const float4*>(W1 + c*16);
        float4 w0v = __ldg(&wr[0]);
        float4 w1v = __ldg(&wr[1]);
        float4 w2v = __ldg(&wr[2]);
        float4 w3v = __ldg(&wr[3]);
        acc0.x = fmaf(tc, w0v.x, acc0.x); acc0.y = fmaf(tc, w0v.y, acc0.y);
        acc0.z = fmaf(tc, w0v.z, acc0.z); acc0.w = fmaf(tc, w0v.w, acc0.w);
        acc1.x = fmaf(tc, w1v.x, acc1.x); acc1.y = fmaf(tc, w1v.y, acc1.y);
        acc1.z = fmaf(tc, w1v.z, acc1.z); acc1.w = fmaf(tc, w1v.w, acc1.w);
        acc2.x = fmaf(tc, w2v.x, acc2.x); acc2.y = fmaf(tc, w2v.y, acc2.y);
        acc2.z = fmaf(tc, w2v.z, acc2.z); acc2.w = fmaf(tc, w2v.w, acc2.w);
        acc3.x = fmaf(tc, w3v.x, acc3.x); acc3.y = fmaf(tc, w3v.y, acc3.y);
        acc3.z = fmaf(tc, w3v.z, acc3.z); acc3.w = fmaf(tc, w3v.w, acc3.w);
    }
    float u[16] = {acc0.x,acc0.y,acc0.z,acc0.w, acc1.x,acc1.y,acc1.z,acc1.w,
                   acc2.x,acc2.y,acc2.z,acc2.w, acc3.x,acc3.y,acc3.z,acc3.w};
    {
        float m=0.f;
        #pragma unroll
        for (int c=0;c<16;c++) m += u[c];
        m *= (1.f/16.f);
        float v=0.f;
        #pragma unroll
        for (int c=0;c<16;c++){ float dd=u[c]-m; v = fmaf(dd,dd,v); }
        v *= (1.f/16.f);
        float inv = rsqrtf(v + 1e-5f);
        #pragma unroll
        for (int g=0; g<4; g++){
            float4 gg = __ldg(&g1_4[g]);
            float4 bb = __ldg(&be1_4[g]);
            u[4*g+0] = lrelu(fmaf((u[4*g+0]-m)*inv, gg.x, bb.x));
            u[4*g+1] = lrelu(fmaf((u[4*g+1]-m)*inv, gg.y, bb.y));
            u[4*g+2] = lrelu(fmaf((u[4*g+2]-m)*inv, gg.z, bb.z));
            u[4*g+3] = lrelu(fmaf((u[4*g+3]-m)*inv, gg.w, bb.w));
        }
    }
    float4* o4 = reinterpret_cast<float4*>(g_feat + (size_t)i*16);
    o4[0] = make_float4(u[0],u[1],u[2],u[3]);
    o4[1] = make_float4(u[4],u[5],u[6],u[7]);
    o4[2] = make_float4(u[8],u[9],u[10],u[11]);
    o4[3] = make_float4(u[12],u[13],u[14],u[15]);
}

// ---------------------------------------------------------------------------
// Kernel B: pointconv1 (K=16 NN of 512 queries over 1024 pts) + fused squeeze
// Persistent grid of 444 blocks (148 SMs x occ 3). 16384 chunks of 8 queries;
// contiguous runs of 36/37 chunks per block.
// ---------------------------------------------------------------------------
#define KB_BLOCKS 444

__global__ void __launch_bounds__(256, 3) kB(
    const float* __restrict__ pc,
    const float* __restrict__ Wp, const float* __restrict__ bp,
    const float* __restrict__ Ws, const float* __restrict__ bsv)
{
    __shared__ __align__(16) float4 sp4[1024];
    __shared__ __align__(16) float  sg[8][16][20];
    __shared__ __align__(16) int    sidxs[8][32];
    __shared__ __align__(16) float  smx[8][32];

    int tid  = threadIdx.x;
    int lane = tid & 31;
    int w    = tid >> 5;
    int bid  = blockIdx.x;

    // contiguous chunk partition: 16384 = 400*37 + 44*36
    int start, cnt;
    if (bid < 400){ start = bid*37;               cnt = 37; }
    else          { start = 14800 + (bid-400)*36; cnt = 36; }

    // packed per-lane GEMM weights: lane = output channel
    unsigned long long wp[9];
    #pragma unroll
    for (int c=0;c<9;c++)
        wp[c] = pk(__ldg(&Wp[(2*c)*32 + lane]), __ldg(&Wp[(2*c+1)*32 + lane]));
    float wr18 = __ldg(&Wp[18*32 + lane]);
    unsigned long long accp = pk(__ldg(&bp[lane]), 0.f);

    // squeeze weights: lane handles output j = lane&7 over c in [cb, cb+8)
    int jq = lane & 7, cb = (lane >> 3) * 8;
    unsigned long long wsp[4];
    #pragma unroll
    for (int i=0;i<4;i++)
        wsp[i] = pk(__ldg(&Ws[(cb+2*i)*8 + jq]), __ldg(&Ws[(cb+2*i+1)*8 + jq]));
    float bsq = __ldg(&bsv[jq]);

    int curB = -1;
    for (int ci = start; ci < start + cnt; ci++){
        int b    = ci >> 6;
        int m    = ((ci & 63) << 3) + w;              // this warp's query
        if (b != curB){
            __syncthreads();                           // old sp4 fully consumed
            const float* p = pc + (size_t)b*3072;
            for (int n = tid; n < 1024; n += 256){
                float X = p[n], Y = p[1024+n], Z = p[2048+n];
                sp4[n] = make_float4(X, Y, Z, fmaf(X,X, fmaf(Y,Y, Z*Z)));
            }
            __syncthreads();
            curB = b;
        }

        int qi = 2*m;                                  // xyz1[m] == xyz0[2m]
        float4 q = sp4[qi];

        int kidx = knn16_select<32>(sp4, q.x, q.y, q.z, lane, &sidxs[w][0]);

        // --- full-warp gather into per-warp smem g[16][20] ------------------
        __syncwarp();
        {
            int j = __shfl_sync(FULLM, kidx, lane & 15);
            float* gr = &sg[w][lane & 15][0];
            const float4* fr = reinterpret_cast<const float4*>(
                g_feat + ((size_t)b*1024 + j)*16);
            if (lane < 16){
                float4 xj = sp4[j];
                float4 f0 = fr[0], f1 = fr[1];
                gr[0]=xj.x-q.x; gr[1]=xj.y-q.y; gr[2]=xj.z-q.z;
                gr[3]=f0.x;  gr[4]=f0.y;  gr[5]=f0.z;  gr[6]=f0.w;
                gr[7]=f1.x;  gr[8]=f1.y;  gr[9]=f1.z;  gr[10]=f1.w;
            } else {
                float4 f2v = fr[2], f3 = fr[3];
                gr[11]=f2v.x; gr[12]=f2v.y; gr[13]=f2v.z; gr[14]=f2v.w;
                gr[15]=f3.x;  gr[16]=f3.y;  gr[17]=f3.z;  gr[18]=f3.w;
            }
        }
        __syncwarp();

        // --- GEMM (lane = output channel) via packed FFMA2 + maxpool -------
        float mx = -BIGF;
        #pragma unroll 4
        for (int k=0;k<16;k++){
            const float* gr = &sg[w][k][0];
            ulonglong2 pA = *reinterpret_cast<const ulonglong2*>(gr);
            ulonglong2 pB = *reinterpret_cast<const ulonglong2*>(gr+4);
            ulonglong2 pC = *reinterpret_cast<const ulonglong2*>(gr+8);
            ulonglong2 pD = *reinterpret_cast<const ulonglong2*>(gr+12);
            unsigned long long pE = *reinterpret_cast<const unsigned long long*>(gr+16);
            float  g18 = gr[18];
            unsigned long long acc = accp;
            acc = ffma2(pA.x, wp[0], acc);
            acc = ffma2(pA.y, wp[1], acc);
            acc = ffma2(pB.x, wp[2], acc);
            acc = ffma2(pB.y, wp[3], acc);
            acc = ffma2(pC.x, wp[4], acc);
            acc = ffma2(pC.y, wp[5], acc);
            acc = ffma2(pD.x, wp[6], acc);
            acc = ffma2(pD.y, wp[7], acc);
            acc = ffma2(pE,   wp[8], acc);
            float2 s = upk(acc);
            float a = fmaf(g18, wr18, s.x + s.y);
            mx = fmaxf(mx, lrelu(a));
        }

        // --- fused squeeze via smem transpose: fs = lrelu(mx @ Ws + bs) -----
        smx[w][lane] = mx;
        __syncwarp();
        const unsigned long long* mp =
            reinterpret_cast<const unsigned long long*>(&smx[w][cb]);
        unsigned long long s2 = pk(0.f, 0.f);
        s2 = ffma2(mp[0], wsp[0], s2);
        s2 = ffma2(mp[1], wsp[1], s2);
        s2 = ffma2(mp[2], wsp[2], s2);
        s2 = ffma2(mp[3], wsp[3], s2);
        float2 sv = upk(s2);
        float s = sv.x + sv.y;
        s += __shfl_down_sync(FULLM, s, 16);
        s += __shfl_down_sync(FULLM, s, 8);
        if (lane < 8)
            g_fs[((size_t)b*512 + m)*8 + jq] = lrelu(s + bsq);
    }
}

// ---------------------------------------------------------------------------
// Kernel C: pointconv2 (128 queries, 512 candidates, 11ch -> 128ch) with
// fused per-chunk column-sum. Persistent grid of 444 blocks; 4096 chunks of
// 8 queries (16 chunks/batch), contiguous runs of 9/10 chunks per block.
// ---------------------------------------------------------------------------
#define KC_BLOCKS 444

__global__ void __launch_bounds__(256, 3) kC(
    const float* __restrict__ pc,
    const float* __restrict__ Wc, const float* __restrict__ bc)
{
    __shared__ __align__(16) float4 sp4[512];
    __shared__ __align__(16) float  sf[512*8];
    __shared__ __align__(16) float  sg[8][16][12];
    __shared__ __align__(16) int    sidxs[8][32];
    __shared__ float  sacc[8][128];

    int tid  = threadIdx.x;
    int lane = tid & 31;
    int w    = tid >> 5;
    int bid  = blockIdx.x;

    // contiguous chunk partition: 4096 = 100*10 + 344*9
    int start, cnt;
    if (bid < 100){ start = bid*10;              cnt = 10; }
    else          { start = 1000 + (bid-100)*9;  cnt = 9;  }

    // packed weights for 4 output channels per lane (lane, lane+32, +64, +96)
    unsigned long long wq0[5], wq1[5], wq2[5], wq3[5];
    #pragma unroll
    for (int c=0;c<5;c++){
        wq0[c] = pk(__ldg(&Wc[(2*c)*128 + lane]),      __ldg(&Wc[(2*c+1)*128 + lane]));
        wq1[c] = pk(__ldg(&Wc[(2*c)*128 + lane + 32]), __ldg(&Wc[(2*c+1)*128 + lane + 32]));
        wq2[c] = pk(__ldg(&Wc[(2*c)*128 + lane + 64]), __ldg(&Wc[(2*c+1)*128 + lane + 64]));
        wq3[c] = pk(__ldg(&Wc[(2*c)*128 + lane + 96]), __ldg(&Wc[(2*c+1)*128 + lane + 96]));
    }
    float w10_0 = __ldg(&Wc[10*128 + lane]),      w10_1 = __ldg(&Wc[10*128 + lane + 32]);
    float w10_2 = __ldg(&Wc[10*128 + lane + 64]), w10_3 = __ldg(&Wc[10*128 + lane + 96]);
    unsigned long long bp0 = pk(__ldg(&bc[lane]),     0.f);
    unsigned long long bp1 = pk(__ldg(&bc[lane+32]),  0.f);
    unsigned long long bp2 = pk(__ldg(&bc[lane+64]),  0.f);
    unsigned long long bp3 = pk(__ldg(&bc[lane+96]),  0.f);

    int curB = -1;
    for (int ci = start; ci < start + cnt; ci++){
        int b     = ci >> 4;
        int chunk = ci & 15;
        int m2    = (chunk << 3) + w;                 // this warp's query
        if (b != curB){
            __syncthreads();                           // old sp4/sf consumed
            const float* p = pc + (size_t)b*3072;
            for (int m = tid; m < 512; m += 256){
                float X = p[2*m], Y = p[1024+2*m], Z = p[2048+2*m];
                sp4[m] = make_float4(X, Y, Z, fmaf(X,X, fmaf(Y,Y, Z*Z)));
            }
            const float4* src = reinterpret_cast<const float4*>(g_fs + (size_t)b*4096);
            float4* dst = reinterpret_cast<float4*>(sf);
            for (int t = tid; t < 1024; t += 256) dst[t] = src[t];
            __syncthreads();
            curB = b;
        }

        int qi = 4*m2;                                 // xyz2[m2] == xyz1[4*m2]
        float4 q = sp4[qi];

        int kidx = knn16_select<16>(sp4, q.x, q.y, q.z, lane, &sidxs[w][0]);

        // --- full-warp gather into per-warp smem g[16][12] ------------------
        __syncwarp();
        {
            int j = __shfl_sync(FULLM, kidx, lane & 15);
            float* gr = &sg[w][lane & 15][0];
            const float4* fr = reinterpret_cast<const float4*>(sf + j*8);
            if (lane < 16){
                float4 xj = sp4[j];
                float4 f0 = fr[0];
                gr[0]=xj.x-q.x; gr[1]=xj.y-q.y; gr[2]=xj.z-q.z;
                gr[3]=f0.x; gr[4]=f0.y; gr[5]=f0.z; gr[6]=f0.w;
            } else {
                float4 f1 = fr[1];
                gr[7]=f1.x; gr[8]=f1.y; gr[9]=f1.z; gr[10]=f1.w;
            }
        }
        __syncwarp();

        float mx0=-BIGF, mx1=-BIGF, mx2=-BIGF, mx3=-BIGF;
        #pragma unroll 4
        for (int k=0;k<16;k++){
            const float* gr = &sg[w][k][0];
            ulonglong2 pA = *reinterpret_cast<const ulonglong2*>(gr);     // g0..g3
            ulonglong2 pB = *reinterpret_cast<const ulonglong2*>(gr+4);   // g4..g7
            float4     v2 = *reinterpret_cast<const float4*>(gr+8);       // g8..g11(pad)
            unsigned long long p4 = pk(v2.x, v2.y);
            float g10 = v2.z;
            unsigned long long a0=bp0, a1=bp1, a2=bp2, a3=bp3;
            a0 = ffma2(pA.x, wq0[0], a0); a1 = ffma2(pA.x, wq1[0], a1);
            a2 = ffma2(pA.x, wq2[0], a2); a3 = ffma2(pA.x, wq3[0], a3);
            a0 = ffma2(pA.y, wq0[1], a0); a1 = ffma2(pA.y, wq1[1], a1);
            a2 = ffma2(pA.y, wq2[1], a2); a3 = ffma2(pA.y, wq3[1], a3);
            a0 = ffma2(pB.x, wq0[2], a0); a1 = ffma2(pB.x, wq1[2], a1);
            a2 = ffma2(pB.x, wq2[2], a2); a3 = ffma2(pB.x, wq3[2], a3);
            a0 = ffma2(pB.y, wq0[3], a0); a1 = ffma2(pB.y, wq1[3], a1);
            a2 = ffma2(pB.y, wq2[3], a2); a3 = ffma2(pB.y, wq3[3], a3);
            a0 = ffma2(p4,   wq0[4], a0); a1 = ffma2(p4,   wq1[4], a1);
            a2 = ffma2(p4,   wq2[4], a2); a3 = ffma2(p4,   wq3[4], a3);
            float2 s0 = upk(a0), s1 = upk(a1), s2 = upk(a2), s3 = upk(a3);
            float r0 = fmaf(g10, w10_0, s0.x + s0.y);
            float r1 = fmaf(g10, w10_1, s1.x + s1.y);
            float r2 = fmaf(g10, w10_2, s2.x + s2.y);
            float r3 = fmaf(g10, w10_3, s3.x + s3.y);
            mx0 = fmaxf(mx0, lrelu(r0));
            mx1 = fmaxf(mx1, lrelu(r1));
            mx2 = fmaxf(mx2, lrelu(r2));
            mx3 = fmaxf(mx3, lrelu(r3));
        }

        // deterministic per-chunk reduction of the 8 queries' vectors
        sacc[w][lane]      = mx0;
        sacc[w][lane + 32] = mx1;
        sacc[w][lane + 64] = mx2;
        sacc[w][lane + 96] = mx3;
        __syncthreads();
        if (tid < 128){
            float s = sacc[0][tid];
            #pragma unroll
            for (int ww=1; ww<8; ww++) s += sacc[ww][tid];
            g_psum[((size_t)b*16 + chunk)*128 + tid] = s;
        }
        __syncthreads();                                // sacc reuse barrier
    }
}

// ---------------------------------------------------------------------------
// Kernel D: out[b] = (sum of 16 chunk psums)/128 @ We + be
// ---------------------------------------------------------------------------
__global__ void __launch_bounds__(256) kD(
    const float* __restrict__ We, const float* __restrict__ be,
    float* __restrict__ out)
{
    __shared__ float sbar[128];
    int b = blockIdx.x, tid = threadIdx.x;
    if (tid < 128){
        const float* ps = g_psum + (size_t)b*16*128 + tid;
        float s = 0.f;
        #pragma unroll
        for (int k=0;k<16;k++) s += ps[k*128];
        sbar[tid] = s * (1.f/128.f);
    }
    __syncthreads();
    float acc = __ldg(&be[tid]);
    #pragma unroll 8
    for (int c=0;c<128;c++) acc = fmaf(sbar[c], __ldg(&We[c*256 + tid]), acc);
    out[(size_t)b*256 + tid] = acc;
}

// ---------------------------------------------------------------------------
extern "C" void kernel_launch(void* const* d_in, const int* in_sizes, int n_in,
                              void* d_out, int out_size)
{
    (void)in_sizes; (void)n_in; (void)out_size;
    const float* pc  = (const float*)d_in[0];
    const float* W0  = (const float*)d_in[1];
    const float* b0  = (const float*)d_in[2];
    const float* g0  = (const float*)d_in[3];
    const float* be0 = (const float*)d_in[4];
    const float* W1  = (const float*)d_in[5];
    const float* b1  = (const float*)d_in[6];
    const float* g1  = (const float*)d_in[7];
    const float* be1 = (const float*)d_in[8];
    const float* Wp  = (const float*)d_in[9];
    const float* bp  = (const float*)d_in[10];
    const float* Ws  = (const float*)d_in[11];
    const float* bsv = (const float*)d_in[12];
    const float* Wc  = (const float*)d_in[13];
    const float* bc  = (const float*)d_in[14];
    const float* We  = (const float*)d_in[15];
    const float* be  = (const float*)d_in[16];
    float* out = (float*)d_out;

    kA<<<1024, 256>>>(pc, W0, b0, g0, be0, W1, b1, g1, be1);
    kB<<<KB_BLOCKS, 256>>>(pc, Wp, bp, Ws, bsv);
    kC<<<KC_BLOCKS, 256>>>(pc, Wc, bc);
    kD<<<256, 256>>>(We, be, out);
}